// round 10
// baseline (speedup 1.0000x reference)
#include <cuda_runtime.h>
#include <cuda_fp16.h>
#include <math.h>
#include <stdint.h>

#define B_ 8
#define H_ 512
#define L_ 4096
#define N_ 32
#define HN (H_ * N_)
#define O_ (2 * H_)

// ---------------- scratch (__device__ globals) -----------------------------
__device__ float d_wr[HN], d_wi[HN], d_csr[HN], d_csi[HN];
__device__ __half d_g[(size_t)B_ * H_ * L_];      // natural layout [b][h][l]
__device__ __half d_Wf[(size_t)O_ * H_];          // single fp16 W plane

// ---------------------------------------------------------------------------
__device__ __forceinline__ uint32_t smem_u32(const void* p) {
    uint32_t a;
    asm("{ .reg .u64 t; cvta.to.shared.u64 t, %1; cvt.u32.u64 %0, t; }"
        : "=r"(a) : "l"(p));
    return a;
}

#define CP_ASYNC16(dst, src) \
    asm volatile("cp.async.cg.shared.global [%0], [%1], 16;" :: "r"(dst), "l"(src))
#define CP_COMMIT() asm volatile("cp.async.commit_group;" ::: "memory")
#define CP_WAIT1()  asm volatile("cp.async.wait_group 1;" ::: "memory")
#define CP_WAIT0()  asm volatile("cp.async.wait_group 0;" ::: "memory")

__device__ __forceinline__ void ldsm4(uint32_t* r, uint32_t addr) {
    asm volatile("ldmatrix.sync.aligned.m8n8.x4.shared.b16 {%0,%1,%2,%3}, [%4];"
                 : "=r"(r[0]), "=r"(r[1]), "=r"(r[2]), "=r"(r[3]) : "r"(addr));
}
__device__ __forceinline__ void ldsm4t(uint32_t* r, uint32_t addr) {
    asm volatile("ldmatrix.sync.aligned.m8n8.x4.trans.shared.b16 {%0,%1,%2,%3}, [%4];"
                 : "=r"(r[0]), "=r"(r[1]), "=r"(r[2]), "=r"(r[3]) : "r"(addr));
}

__device__ __forceinline__ void mma16816(float* d, const uint32_t* a,
                                         uint32_t b0, uint32_t b1) {
    asm volatile("mma.sync.aligned.m16n8k16.row.col.f32.f16.f16.f32 "
                 "{%0,%1,%2,%3}, {%4,%5,%6,%7}, {%8,%9}, {%0,%1,%2,%3};"
                 : "+f"(d[0]), "+f"(d[1]), "+f"(d[2]), "+f"(d[3])
                 : "r"(a[0]), "r"(a[1]), "r"(a[2]), "r"(a[3]), "r"(b0), "r"(b1));
}

// ---------------------------------------------------------------------------
// Kernel 1: per (h,n) precompute  w = exp(dt*A),  2*Cs = 2*C*(w-1)/A
// ---------------------------------------------------------------------------
__global__ void prep_kernel(const float* __restrict__ log_dt,
                            const float* __restrict__ log_A_real,
                            const float* __restrict__ A_imag,
                            const float* __restrict__ C)
{
    int idx = blockIdx.x * blockDim.x + threadIdx.x;
    if (idx >= HN) return;
    int h = idx / N_;
    float dt = expf(log_dt[h]);
    float ar = -expf(log_A_real[idx]);
    float ai = A_imag[idx];
    float mag = expf(dt * ar);
    float wr = mag * cosf(dt * ai);
    float wi = mag * sinf(dt * ai);
    float den = ar * ar + ai * ai;
    float nr = wr - 1.0f, ni = wi;
    float qr = (nr * ar + ni * ai) / den;
    float qi = (ni * ar - nr * ai) / den;
    float Cr = C[2 * idx], Ci = C[2 * idx + 1];
    d_wr[idx]  = wr;
    d_wi[idx]  = wi;
    d_csr[idx] = 2.0f * (Cr * qr - Ci * qi);
    d_csi[idx] = 2.0f * (Cr * qi + Ci * qr);
}

// ---------------------------------------------------------------------------
// Kernel 1b: convert W to fp16
// ---------------------------------------------------------------------------
__global__ void wconv_kernel(const float* __restrict__ W)
{
    int idx = blockIdx.x * blockDim.x + threadIdx.x;
    if (idx >= O_ * H_) return;
    d_Wf[idx] = __float2half(W[idx]);
}

// ---------------------------------------------------------------------------
// Kernel 2: scan, z-form (z = Cs*x, z' = w*z + Cs*u, contribution = Re(z)).
// No shuffles in the hot loop: every lane holds the group's 32 u values in
// 8 float4 regs (uniform 128B loads, double-buffered one group ahead).
// Per step: 6 fma-class + 1 STS. Per group: lane t column-sums 32
// contributions, adds D*u, GELU, coalesced fp16 store.
// ---------------------------------------------------------------------------
__global__ __launch_bounds__(256) void scan_kernel(const float* __restrict__ u,
                                                   const float* __restrict__ D)
{
    __shared__ float red[8][32][34];   // [warp][t][lane]

    const int tid  = threadIdx.x;
    const int wid  = tid >> 5;
    const int lane = tid & 31;

    const int gw = blockIdx.x * 8 + wid;
    const int b  = gw >> 9;
    const int h  = gw & 511;

    const int idx = h * N_ + lane;
    const float wr  = d_wr[idx], wi = d_wi[idx];
    const float csr = d_csr[idx], csi = d_csi[idx];
    const float Dh  = D[h];

    const float*  up  = u + ((size_t)b * H_ + h) * L_;
    const float4* up4 = (const float4*)up;
    __half*       gp  = d_g + ((size_t)b * H_ + h) * L_;

    float zr = 0.0f, zi = 0.0f;

    float4 bufA[8], bufB[8];
    #pragma unroll
    for (int i = 0; i < 8; i++) bufA[i] = up4[i];      // group 0

    for (int l0 = 0; l0 < L_; l0 += 32) {
        if (l0 + 32 < L_) {
            const float4* nxt = up4 + (l0 >> 2) + 8;
            #pragma unroll
            for (int i = 0; i < 8; i++) bufB[i] = nxt[i];
        }
        float uv = up[l0 + lane];          // for D-skip (L1 hit, coalesced)

        #pragma unroll
        for (int q = 0; q < 8; q++) {
            float uu0 = bufA[q].x, uu1 = bufA[q].y;
            float uu2 = bufA[q].z, uu3 = bufA[q].w;
            #pragma unroll
            for (int r = 0; r < 4; r++) {
                float ut = (r == 0) ? uu0 : (r == 1) ? uu1 : (r == 2) ? uu2 : uu3;
                float cur = csr * ut;
                float cui = csi * ut;
                float t0  = fmaf(-wi, zi, cur);
                float t1  = fmaf( wi, zr, cui);
                float nzr = fmaf(wr, zr, t0);
                float nzi = fmaf(wr, zi, t1);
                zr = nzr; zi = nzi;
                red[wid][q * 4 + r][lane] = zr;        // contribution = Re(z)
            }
        }
        __syncwarp();
        const float2* rp = (const float2*)red[wid][lane];
        float s0 = 0.0f, s1 = 0.0f, s2 = 0.0f, s3 = 0.0f;
        #pragma unroll
        for (int j = 0; j < 8; j++) {
            float2 a = rp[2 * j], c2 = rp[2 * j + 1];
            s0 += a.x; s1 += a.y; s2 += c2.x; s3 += c2.y;
        }
        float y  = fmaf(Dh, uv, (s0 + s1) + (s2 + s3));
        float gv = 0.5f * y * (1.0f + erff(y * 0.70710678118654752f));
        gp[l0 + lane] = __float2half(gv);
        __syncwarp();
        #pragma unroll
        for (int i = 0; i < 8; i++) bufA[i] = bufB[i];
    }
}

// ---------------------------------------------------------------------------
// Kernel 3: mma.sync fp16 GEMM + GLU, single pass (unchanged from round 9).
// CTA: M=128 (a + gate channel halves), N=128 l-cols, BK=32, 3-stage
// cp.async pipeline, 8 warps (4M x 2N), warp tile 32x64, 2 CTAs/SM.
// ---------------------------------------------------------------------------
#define BK 32
#define SSTR 80                              // A rows: 64B + 16B pad
#define SSTRB 272                            // B rows: 256B + 16B pad
#define TILE_A 10240                         // 128 * 80
#define TILE_B (BK * SSTRB)                  // 8704
#define OFF_B  TILE_A
#define STAGEB (TILE_A + TILE_B)             // 18944
#define NSTAGE (H_ / BK)                     // 16
#define SMEM_BYTES (3 * STAGEB)              // 56832
#define BSRC_STRIDE ((size_t)BK * L_ * 2)    // 262144 bytes per stage

__global__ __launch_bounds__(256, 2) void gemm_glu_mma(const float* __restrict__ bias,
                                                       float* __restrict__ out)
{
    extern __shared__ char smem[];
    const int tid  = threadIdx.x;
    const int wid  = tid >> 5;
    const int lane = tid & 31;

    const int b  = blockIdx.x >> 5;
    const int l0 = (blockIdx.x & 31) * 128;
    const int h0 = blockIdx.y * 64;

    const uint32_t sb = smem_u32(smem);
    const int wm = wid >> 1;
    const int wn = wid & 1;

    uint32_t aoff[2], boff[4];
    {
        int rr0 = wm * 32 + (lane & 15);
        int ka  = (lane >> 4) << 4;
        aoff[0] = (uint32_t)((rr0 +  0) * SSTR + ka);
        aoff[1] = (uint32_t)((rr0 + 16) * SSTR + ka);
        int rowb = (lane & 15) * SSTRB;
        int nbase = wn * 64 + ((lane >> 4) << 3);
        #pragma unroll
        for (int jb = 0; jb < 4; jb++)
            boff[jb] = (uint32_t)(OFF_B + rowb + (nbase + jb * 16) * 2);
    }

    const char* srcs[4];
    uint32_t    dsts[4];
    #pragma unroll
    for (int j = 0; j < 2; j++) {
        int id  = tid + 256 * j;
        int row = id >> 2;
        int seg = id & 3;
        int arow = h0 + row + ((row >= 64) ? 448 : 0);
        srcs[j] = (const char*)(d_Wf + (size_t)arow * H_) + seg * 16;
        dsts[j] = sb + row * SSTR + seg * 16;
    }
    #pragma unroll
    for (int j = 2; j < 4; j++) {
        int id  = tid + 256 * (j - 2);
        int row = id >> 4;
        int seg = id & 15;
        const __half* base = d_g + (size_t)b * H_ * L_;
        srcs[j] = (const char*)(base + (size_t)row * L_ + l0) + seg * 16;
        dsts[j] = sb + OFF_B + row * SSTRB + seg * 16;
    }

    #pragma unroll
    for (int j = 0; j < 4; j++) CP_ASYNC16(dsts[j], srcs[j]);
    CP_COMMIT();
    #pragma unroll
    for (int j = 0; j < 2; j++) CP_ASYNC16(dsts[j] + STAGEB, srcs[j] + 64);
    #pragma unroll
    for (int j = 2; j < 4; j++) CP_ASYNC16(dsts[j] + STAGEB, srcs[j] + BSRC_STRIDE);
    CP_COMMIT();

    float acc[2][8][4];
    #pragma unroll
    for (int mf = 0; mf < 2; mf++)
        #pragma unroll
        for (int nf = 0; nf < 8; nf++)
            #pragma unroll
            for (int e = 0; e < 4; e++) acc[mf][nf][e] = 0.0f;

    for (int s = 0; s < NSTAGE; s++) {
        if (s == NSTAGE - 1) { CP_WAIT0(); } else { CP_WAIT1(); }
        __syncthreads();

        const uint32_t st = sb + (uint32_t)(s % 3) * STAGEB;

        #pragma unroll
        for (int ks = 0; ks < 2; ks++) {
            const uint32_t ksoA = (uint32_t)(ks * 32);
            const uint32_t ksoB = (uint32_t)(ks * 16 * SSTRB);
            uint32_t aF[2][4], bF[4][4];
            #pragma unroll
            for (int mf = 0; mf < 2; mf++)
                ldsm4(aF[mf], st + aoff[mf] + ksoA);
            #pragma unroll
            for (int jb = 0; jb < 4; jb++)
                ldsm4t(bF[jb], st + boff[jb] + ksoB);
            #pragma unroll
            for (int mf = 0; mf < 2; mf++)
                #pragma unroll
                for (int jb = 0; jb < 4; jb++)
                    #pragma unroll
                    for (int hh = 0; hh < 2; hh++)
                        mma16816(acc[mf][jb * 2 + hh], aF[mf],
                                 bF[jb][2 * hh], bF[jb][2 * hh + 1]);
        }

        if (s + 2 < NSTAGE) {
            uint32_t dbo = (uint32_t)((s + 2) % 3) * STAGEB;
            #pragma unroll
            for (int j = 0; j < 2; j++)
                CP_ASYNC16(dsts[j] + dbo, srcs[j] + (size_t)(s + 2) * 64);
            #pragma unroll
            for (int j = 2; j < 4; j++)
                CP_ASYNC16(dsts[j] + dbo, srcs[j] + (size_t)(s + 2) * BSRC_STRIDE);
            CP_COMMIT();
        }
    }
    __syncthreads();

    // ---- epilogue: GLU ----
    float* sg = (float*)smem;               // [64][130] f32
    const int r0 = (lane >> 2);
    const int c0 = (lane & 3) * 2;

    if (wm >= 2) {
        #pragma unroll
        for (int mf = 0; mf < 2; mf++) {
            int row = wm * 32 + mf * 16 + r0;     // 64..127
            int grow = row - 64;
            float bg  = bias[H_ + h0 + grow];
            float bg2 = bias[H_ + h0 + grow + 8];
            #pragma unroll
            for (int nf = 0; nf < 8; nf++) {
                int col = wn * 64 + nf * 8 + c0;
                *(float2*)&sg[grow * 130 + col] =
                    make_float2(acc[mf][nf][0] + bg, acc[mf][nf][1] + bg);
                *(float2*)&sg[(grow + 8) * 130 + col] =
                    make_float2(acc[mf][nf][2] + bg2, acc[mf][nf][3] + bg2);
            }
        }
    }
    __syncthreads();
    if (wm < 2) {
        #pragma unroll
        for (int mf = 0; mf < 2; mf++) {
            int row = wm * 32 + mf * 16 + r0;     // 0..63
            int h  = h0 + row;
            float ba  = bias[h];
            float ba2 = bias[h + 8];
            float* ob  = out + ((size_t)b * H_ + h) * L_ + l0;
            float* ob2 = out + ((size_t)b * H_ + h + 8) * L_ + l0;
            #pragma unroll
            for (int nf = 0; nf < 8; nf++) {
                int col = wn * 64 + nf * 8 + c0;
                float2 g0 = *(const float2*)&sg[row * 130 + col];
                float2 g1 = *(const float2*)&sg[(row + 8) * 130 + col];
                float2 o0, o1;
                o0.x = (acc[mf][nf][0] + ba)  / (1.0f + expf(-g0.x));
                o0.y = (acc[mf][nf][1] + ba)  / (1.0f + expf(-g0.y));
                o1.x = (acc[mf][nf][2] + ba2) / (1.0f + expf(-g1.x));
                o1.y = (acc[mf][nf][3] + ba2) / (1.0f + expf(-g1.y));
                *(float2*)(ob  + col) = o0;
                *(float2*)(ob2 + col) = o1;
            }
        }
    }
}

// ---------------------------------------------------------------------------
extern "C" void kernel_launch(void* const* d_in, const int* in_sizes, int n_in,
                              void* d_out, int out_size)
{
    const float* u          = (const float*)d_in[0];
    const float* log_dt     = (const float*)d_in[1];
    const float* log_A_real = (const float*)d_in[2];
    const float* A_imag     = (const float*)d_in[3];
    const float* C          = (const float*)d_in[4];
    const float* D          = (const float*)d_in[5];
    const float* W_out      = (const float*)d_in[6];
    const float* b_out      = (const float*)d_in[7];
    float* out = (float*)d_out;

    static bool attr_set = false;
    if (!attr_set) {
        cudaFuncSetAttribute(gemm_glu_mma, cudaFuncAttributeMaxDynamicSharedMemorySize,
                             SMEM_BYTES);
        attr_set = true;
    }

    prep_kernel<<<(HN + 127) / 128, 128>>>(log_dt, log_A_real, A_imag, C);
    wconv_kernel<<<(O_ * H_ + 255) / 256, 256>>>(W_out);
    scan_kernel<<<(B_ * H_) / 8, 256>>>(u, D);

    dim3 grid(B_ * (L_ / 128), H_ / 64);    // (256, 8)
    gemm_glu_mma<<<grid, 256, SMEM_BYTES>>>(b_out, out);
}

// round 11
// speedup vs baseline: 1.2148x; 1.2148x over previous
#include <cuda_runtime.h>
#include <cuda_fp16.h>
#include <math.h>
#include <stdint.h>

#define B_ 8
#define H_ 512
#define L_ 4096
#define N_ 32
#define HN (H_ * N_)
#define O_ (2 * H_)

typedef unsigned long long ull;

// ---------------- scratch (__device__ globals) -----------------------------
__device__ float d_wr[HN], d_wi[HN], d_csr[HN], d_csi[HN];
__device__ __half d_g[(size_t)B_ * H_ * L_];      // natural layout [b][h][l]
__device__ __half d_Wf[(size_t)O_ * H_];          // single fp16 W plane

// ---------------------------------------------------------------------------
__device__ __forceinline__ uint32_t smem_u32(const void* p) {
    uint32_t a;
    asm("{ .reg .u64 t; cvta.to.shared.u64 t, %1; cvt.u32.u64 %0, t; }"
        : "=r"(a) : "l"(p));
    return a;
}

#define CP_ASYNC16(dst, src) \
    asm volatile("cp.async.cg.shared.global [%0], [%1], 16;" :: "r"(dst), "l"(src))
#define CP_COMMIT() asm volatile("cp.async.commit_group;" ::: "memory")
#define CP_WAIT1()  asm volatile("cp.async.wait_group 1;" ::: "memory")
#define CP_WAIT0()  asm volatile("cp.async.wait_group 0;" ::: "memory")

__device__ __forceinline__ void ldsm4(uint32_t* r, uint32_t addr) {
    asm volatile("ldmatrix.sync.aligned.m8n8.x4.shared.b16 {%0,%1,%2,%3}, [%4];"
                 : "=r"(r[0]), "=r"(r[1]), "=r"(r[2]), "=r"(r[3]) : "r"(addr));
}
__device__ __forceinline__ void ldsm4t(uint32_t* r, uint32_t addr) {
    asm volatile("ldmatrix.sync.aligned.m8n8.x4.trans.shared.b16 {%0,%1,%2,%3}, [%4];"
                 : "=r"(r[0]), "=r"(r[1]), "=r"(r[2]), "=r"(r[3]) : "r"(addr));
}

__device__ __forceinline__ void mma16816(float* d, const uint32_t* a,
                                         uint32_t b0, uint32_t b1) {
    asm volatile("mma.sync.aligned.m16n8k16.row.col.f32.f16.f16.f32 "
                 "{%0,%1,%2,%3}, {%4,%5,%6,%7}, {%8,%9}, {%0,%1,%2,%3};"
                 : "+f"(d[0]), "+f"(d[1]), "+f"(d[2]), "+f"(d[3])
                 : "r"(a[0]), "r"(a[1]), "r"(a[2]), "r"(a[3]), "r"(b0), "r"(b1));
}

// ---- packed fp32x2 (B300 FFMA2 path) ----
__device__ __forceinline__ ull pk2(float a, float b) {
    ull r;
    asm("mov.b64 %0, {%1, %2};" : "=l"(r) : "f"(a), "f"(b));
    return r;
}
#define FMA2(d, a, b, c) \
    asm("fma.rn.f32x2 %0, %1, %2, %3;" : "=l"(d) : "l"(a), "l"(b), "l"(c))
#define MUL2(d, a, b) \
    asm("mul.rn.f32x2 %0, %1, %2;" : "=l"(d) : "l"(a), "l"(b))

// ---------------------------------------------------------------------------
// Kernel 1: per (h,n) precompute  w = exp(dt*A),  2*Cs = 2*C*(w-1)/A
// ---------------------------------------------------------------------------
__global__ void prep_kernel(const float* __restrict__ log_dt,
                            const float* __restrict__ log_A_real,
                            const float* __restrict__ A_imag,
                            const float* __restrict__ C)
{
    int idx = blockIdx.x * blockDim.x + threadIdx.x;
    if (idx >= HN) return;
    int h = idx / N_;
    float dt = expf(log_dt[h]);
    float ar = -expf(log_A_real[idx]);
    float ai = A_imag[idx];
    float mag = expf(dt * ar);
    float wr = mag * cosf(dt * ai);
    float wi = mag * sinf(dt * ai);
    float den = ar * ar + ai * ai;
    float nr = wr - 1.0f, ni = wi;
    float qr = (nr * ar + ni * ai) / den;
    float qi = (ni * ar - nr * ai) / den;
    float Cr = C[2 * idx], Ci = C[2 * idx + 1];
    d_wr[idx]  = wr;
    d_wi[idx]  = wi;
    d_csr[idx] = 2.0f * (Cr * qr - Ci * qi);
    d_csi[idx] = 2.0f * (Cr * qi + Ci * qr);
}

// ---------------------------------------------------------------------------
// Kernel 1b: convert W to fp16
// ---------------------------------------------------------------------------
__global__ void wconv_kernel(const float* __restrict__ W)
{
    int idx = blockIdx.x * blockDim.x + threadIdx.x;
    if (idx >= O_ * H_) return;
    d_Wf[idx] = __float2half(W[idx]);
}

// ---------------------------------------------------------------------------
// Kernel 2: scan, z-form, packed f32x2, TWO sequences per warp.
// Warp = (h, batch-pair). Lane = mode n, state packed (seq0,seq1).
// Per step: 1 LDS.64 (u pair broadcast) + 6 f32x2 + 1 STS.64.
// Per group: lane t column-sums both seqs, D-skip, GELU x2, fp16 stores.
// ---------------------------------------------------------------------------
#define RPAD 34                         // float2 row stride (16B aligned)
#define SCAN_RED  (8 * 32 * RPAD)       // float2 count
#define SCAN_US   (8 * 36)              // float2 count
#define SCAN_SMEM ((SCAN_RED + SCAN_US) * 8)

__global__ __launch_bounds__(256) void scan_kernel(const float* __restrict__ u,
                                                   const float* __restrict__ D)
{
    extern __shared__ char sm2[];
    float2* red_all = (float2*)sm2;
    float2* us_all  = red_all + SCAN_RED;

    const int tid  = threadIdx.x;
    const int wid  = tid >> 5;
    const int lane = tid & 31;

    const int gw   = blockIdx.x * 8 + wid;   // 0..2047
    const int pair = gw >> 9;                // 0..3
    const int h    = gw & 511;
    const int b0   = pair * 2;

    ull*    redw = (ull*)(red_all + wid * (32 * RPAD));
    float2* usw  = us_all + wid * 36;
    ull*    usp  = (ull*)usw;

    const int idx = h * N_ + lane;
    const float wr  = d_wr[idx],  wi  = d_wi[idx];
    const float csr = d_csr[idx], csi = d_csi[idx];
    const float Dh  = D[h];

    const ull WR2  = pk2(wr, wr);
    const ull WI2  = pk2(wi, wi);
    const ull NWI2 = pk2(-wi, -wi);
    const ull CSR2 = pk2(csr, csr);
    const ull CSI2 = pk2(csi, csi);

    const float* up0 = u + ((size_t)b0 * H_ + h) * L_;
    const float* up1 = u + ((size_t)(b0 + 1) * H_ + h) * L_;
    __half* gp0 = d_g + ((size_t)b0 * H_ + h) * L_;
    __half* gp1 = d_g + ((size_t)(b0 + 1) * H_ + h) * L_;

    ull ZR = 0ull, ZI = 0ull;

    // 2-deep u prefetch for both sequences
    float u0a = up0[lane],      u1a = up1[lane];
    float u0b = up0[32 + lane], u1b = up1[32 + lane];

    for (int l0 = 0; l0 < L_; l0 += 32) {
        float uv0 = u0a, uv1 = u1a;
        u0a = u0b; u1a = u1b;
        if (l0 + 64 < L_) {
            u0b = up0[l0 + 64 + lane];
            u1b = up1[l0 + 64 + lane];
        }
        usw[lane] = make_float2(uv0, uv1);
        __syncwarp();

        #pragma unroll
        for (int t = 0; t < 32; t++) {
            ull UU = usp[t];                 // broadcast LDS.64
            ull CUR, CUI, T0, T1;
            MUL2(CUR, CSR2, UU);
            MUL2(CUI, CSI2, UU);
            FMA2(T0, NWI2, ZI, CUR);
            FMA2(T1, WI2,  ZR, CUI);
            FMA2(ZR, WR2,  ZR, T0);
            FMA2(ZI, WR2,  ZI, T1);
            redw[t * RPAD + lane] = ZR;      // packed (c0,c1) contribution
        }
        __syncwarp();

        // lane t sums 32 mode-contributions for both seqs
        const float4* rp = (const float4*)(redw + lane * RPAD);
        float s0a = 0.0f, s0b = 0.0f, s1a = 0.0f, s1b = 0.0f;
        #pragma unroll
        for (int j = 0; j < 16; j++) {
            float4 v = rp[j];
            s0a += v.x; s1a += v.y;
            s0b += v.z; s1b += v.w;
        }
        float y0 = fmaf(Dh, uv0, s0a + s0b);
        float y1 = fmaf(Dh, uv1, s1a + s1b);
        float g0 = 0.5f * y0 * (1.0f + erff(y0 * 0.70710678118654752f));
        float g1 = 0.5f * y1 * (1.0f + erff(y1 * 0.70710678118654752f));
        gp0[l0 + lane] = __float2half(g0);
        gp1[l0 + lane] = __float2half(g1);
        __syncwarp();
    }
}

// ---------------------------------------------------------------------------
// Kernel 3: mma.sync fp16 GEMM + GLU, single pass (unchanged from round 9).
// CTA: M=128 (a + gate channel halves), N=128 l-cols, BK=32, 3-stage
// cp.async pipeline, 8 warps (4M x 2N), warp tile 32x64, 2 CTAs/SM.
// ---------------------------------------------------------------------------
#define BK 32
#define SSTR 80                              // A rows: 64B + 16B pad
#define SSTRB 272                            // B rows: 256B + 16B pad
#define TILE_A 10240                         // 128 * 80
#define TILE_B (BK * SSTRB)                  // 8704
#define OFF_B  TILE_A
#define STAGEB (TILE_A + TILE_B)             // 18944
#define NSTAGE (H_ / BK)                     // 16
#define SMEM_BYTES (3 * STAGEB)              // 56832
#define BSRC_STRIDE ((size_t)BK * L_ * 2)    // 262144 bytes per stage

__global__ __launch_bounds__(256, 2) void gemm_glu_mma(const float* __restrict__ bias,
                                                       float* __restrict__ out)
{
    extern __shared__ char smem[];
    const int tid  = threadIdx.x;
    const int wid  = tid >> 5;
    const int lane = tid & 31;

    const int b  = blockIdx.x >> 5;
    const int l0 = (blockIdx.x & 31) * 128;
    const int h0 = blockIdx.y * 64;

    const uint32_t sb = smem_u32(smem);
    const int wm = wid >> 1;
    const int wn = wid & 1;

    uint32_t aoff[2], boff[4];
    {
        int rr0 = wm * 32 + (lane & 15);
        int ka  = (lane >> 4) << 4;
        aoff[0] = (uint32_t)((rr0 +  0) * SSTR + ka);
        aoff[1] = (uint32_t)((rr0 + 16) * SSTR + ka);
        int rowb = (lane & 15) * SSTRB;
        int nbase = wn * 64 + ((lane >> 4) << 3);
        #pragma unroll
        for (int jb = 0; jb < 4; jb++)
            boff[jb] = (uint32_t)(OFF_B + rowb + (nbase + jb * 16) * 2);
    }

    const char* srcs[4];
    uint32_t    dsts[4];
    #pragma unroll
    for (int j = 0; j < 2; j++) {
        int id  = tid + 256 * j;
        int row = id >> 2;
        int seg = id & 3;
        int arow = h0 + row + ((row >= 64) ? 448 : 0);
        srcs[j] = (const char*)(d_Wf + (size_t)arow * H_) + seg * 16;
        dsts[j] = sb + row * SSTR + seg * 16;
    }
    #pragma unroll
    for (int j = 2; j < 4; j++) {
        int id  = tid + 256 * (j - 2);
        int row = id >> 4;
        int seg = id & 15;
        const __half* base = d_g + (size_t)b * H_ * L_;
        srcs[j] = (const char*)(base + (size_t)row * L_ + l0) + seg * 16;
        dsts[j] = sb + OFF_B + row * SSTRB + seg * 16;
    }

    #pragma unroll
    for (int j = 0; j < 4; j++) CP_ASYNC16(dsts[j], srcs[j]);
    CP_COMMIT();
    #pragma unroll
    for (int j = 0; j < 2; j++) CP_ASYNC16(dsts[j] + STAGEB, srcs[j] + 64);
    #pragma unroll
    for (int j = 2; j < 4; j++) CP_ASYNC16(dsts[j] + STAGEB, srcs[j] + BSRC_STRIDE);
    CP_COMMIT();

    float acc[2][8][4];
    #pragma unroll
    for (int mf = 0; mf < 2; mf++)
        #pragma unroll
        for (int nf = 0; nf < 8; nf++)
            #pragma unroll
            for (int e = 0; e < 4; e++) acc[mf][nf][e] = 0.0f;

    for (int s = 0; s < NSTAGE; s++) {
        if (s == NSTAGE - 1) { CP_WAIT0(); } else { CP_WAIT1(); }
        __syncthreads();

        const uint32_t st = sb + (uint32_t)(s % 3) * STAGEB;

        #pragma unroll
        for (int ks = 0; ks < 2; ks++) {
            const uint32_t ksoA = (uint32_t)(ks * 32);
            const uint32_t ksoB = (uint32_t)(ks * 16 * SSTRB);
            uint32_t aF[2][4], bF[4][4];
            #pragma unroll
            for (int mf = 0; mf < 2; mf++)
                ldsm4(aF[mf], st + aoff[mf] + ksoA);
            #pragma unroll
            for (int jb = 0; jb < 4; jb++)
                ldsm4t(bF[jb], st + boff[jb] + ksoB);
            #pragma unroll
            for (int mf = 0; mf < 2; mf++)
                #pragma unroll
                for (int jb = 0; jb < 4; jb++)
                    #pragma unroll
                    for (int hh = 0; hh < 2; hh++)
                        mma16816(acc[mf][jb * 2 + hh], aF[mf],
                                 bF[jb][2 * hh], bF[jb][2 * hh + 1]);
        }

        if (s + 2 < NSTAGE) {
            uint32_t dbo = (uint32_t)((s + 2) % 3) * STAGEB;
            #pragma unroll
            for (int j = 0; j < 2; j++)
                CP_ASYNC16(dsts[j] + dbo, srcs[j] + (size_t)(s + 2) * 64);
            #pragma unroll
            for (int j = 2; j < 4; j++)
                CP_ASYNC16(dsts[j] + dbo, srcs[j] + (size_t)(s + 2) * BSRC_STRIDE);
            CP_COMMIT();
        }
    }
    __syncthreads();

    // ---- epilogue: GLU ----
    float* sg = (float*)smem;               // [64][130] f32
    const int r0 = (lane >> 2);
    const int c0 = (lane & 3) * 2;

    if (wm >= 2) {
        #pragma unroll
        for (int mf = 0; mf < 2; mf++) {
            int row = wm * 32 + mf * 16 + r0;     // 64..127
            int grow = row - 64;
            float bg  = bias[H_ + h0 + grow];
            float bg2 = bias[H_ + h0 + grow + 8];
            #pragma unroll
            for (int nf = 0; nf < 8; nf++) {
                int col = wn * 64 + nf * 8 + c0;
                *(float2*)&sg[grow * 130 + col] =
                    make_float2(acc[mf][nf][0] + bg, acc[mf][nf][1] + bg);
                *(float2*)&sg[(grow + 8) * 130 + col] =
                    make_float2(acc[mf][nf][2] + bg2, acc[mf][nf][3] + bg2);
            }
        }
    }
    __syncthreads();
    if (wm < 2) {
        #pragma unroll
        for (int mf = 0; mf < 2; mf++) {
            int row = wm * 32 + mf * 16 + r0;     // 0..63
            int h  = h0 + row;
            float ba  = bias[h];
            float ba2 = bias[h + 8];
            float* ob  = out + ((size_t)b * H_ + h) * L_ + l0;
            float* ob2 = out + ((size_t)b * H_ + h + 8) * L_ + l0;
            #pragma unroll
            for (int nf = 0; nf < 8; nf++) {
                int col = wn * 64 + nf * 8 + c0;
                float2 g0 = *(const float2*)&sg[row * 130 + col];
                float2 g1 = *(const float2*)&sg[(row + 8) * 130 + col];
                float2 o0, o1;
                o0.x = (acc[mf][nf][0] + ba)  / (1.0f + expf(-g0.x));
                o0.y = (acc[mf][nf][1] + ba)  / (1.0f + expf(-g0.y));
                o1.x = (acc[mf][nf][2] + ba2) / (1.0f + expf(-g1.x));
                o1.y = (acc[mf][nf][3] + ba2) / (1.0f + expf(-g1.y));
                *(float2*)(ob  + col) = o0;
                *(float2*)(ob2 + col) = o1;
            }
        }
    }
}

// ---------------------------------------------------------------------------
extern "C" void kernel_launch(void* const* d_in, const int* in_sizes, int n_in,
                              void* d_out, int out_size)
{
    const float* u          = (const float*)d_in[0];
    const float* log_dt     = (const float*)d_in[1];
    const float* log_A_real = (const float*)d_in[2];
    const float* A_imag     = (const float*)d_in[3];
    const float* C          = (const float*)d_in[4];
    const float* D          = (const float*)d_in[5];
    const float* W_out      = (const float*)d_in[6];
    const float* b_out      = (const float*)d_in[7];
    float* out = (float*)d_out;

    static bool attr_set = false;
    if (!attr_set) {
        cudaFuncSetAttribute(gemm_glu_mma, cudaFuncAttributeMaxDynamicSharedMemorySize,
                             SMEM_BYTES);
        cudaFuncSetAttribute(scan_kernel, cudaFuncAttributeMaxDynamicSharedMemorySize,
                             SCAN_SMEM);
        attr_set = true;
    }

    prep_kernel<<<(HN + 127) / 128, 128>>>(log_dt, log_A_real, A_imag, C);
    wconv_kernel<<<(O_ * H_ + 255) / 256, 256>>>(W_out);

    // 2048 warps (2 sequences each), 8 warps/block
    scan_kernel<<<256, 256, SCAN_SMEM>>>(u, D);

    dim3 grid(B_ * (L_ / 128), H_ / 64);    // (256, 8)
    gemm_glu_mma<<<grid, 256, SMEM_BYTES>>>(b_out, out);
}